// round 15
// baseline (speedup 1.0000x reference)
#include <cuda_runtime.h>
#include <cuda_bf16.h>
#include <cstdint>

// Problem constants
#define DIM_X 1024
#define H1    2048
#define H2    512
#define SL    8192
#define SU    16384
#define K_TRIES 8

// ---------------------------------------------------------------------------
// Device scratch (no allocations allowed). 16B-aligned for cp.async.
// ---------------------------------------------------------------------------
__device__ __align__(16) __nv_bfloat16 g_Xu_hi[(size_t)SU * DIM_X];
__device__ __align__(16) __nv_bfloat16 g_Xu_lo[(size_t)SU * DIM_X];
__device__ __align__(16) __nv_bfloat16 g_Xl_hi[(size_t)SL * DIM_X];
__device__ __align__(16) __nv_bfloat16 g_Xl_lo[(size_t)SL * DIM_X];
__device__ __align__(16) __nv_bfloat16 g_W1_hi[(size_t)DIM_X * H1];
__device__ __align__(16) __nv_bfloat16 g_W1_lo[(size_t)DIM_X * H1];
__device__ __align__(16) __nv_bfloat16 g_W2_hi[(size_t)H1 * H2];
__device__ __align__(16) __nv_bfloat16 g_W2_lo[(size_t)H1 * H2];
__device__ __align__(16) __nv_bfloat16 g_h_hi[(size_t)SU * H1];   // hidden, reused l/u
__device__ __align__(16) __nv_bfloat16 g_h_lo[(size_t)SU * H1];
__device__ __align__(16) float g_feat_l[(size_t)SL * H2];
__device__ int g_a[SU];
__device__ int g_b[SU];

// ---------------------------------------------------------------------------
// helpers
// ---------------------------------------------------------------------------
__device__ __forceinline__ uint32_t pk_bf16(__nv_bfloat16 a, __nv_bfloat16 b) {
    return (uint32_t)__bfloat16_as_ushort(a) | ((uint32_t)__bfloat16_as_ushort(b) << 16);
}

// fp32 -> (hi, lo) bf16 split, vectorized x4
__global__ void cvt_hilo(const float4* __restrict__ in, uint2* __restrict__ hi,
                         uint2* __restrict__ lo, int n4) {
    int i = blockIdx.x * blockDim.x + threadIdx.x;
    if (i >= n4) return;
    float4 f = in[i];
    __nv_bfloat16 h0 = __float2bfloat16(f.x), h1 = __float2bfloat16(f.y);
    __nv_bfloat16 h2 = __float2bfloat16(f.z), h3 = __float2bfloat16(f.w);
    __nv_bfloat16 l0 = __float2bfloat16(f.x - __bfloat162float(h0));
    __nv_bfloat16 l1 = __float2bfloat16(f.y - __bfloat162float(h1));
    __nv_bfloat16 l2 = __float2bfloat16(f.z - __bfloat162float(h2));
    __nv_bfloat16 l3 = __float2bfloat16(f.w - __bfloat162float(h3));
    hi[i] = make_uint2(pk_bf16(h0, h1), pk_bf16(h2, h3));
    lo[i] = make_uint2(pk_bf16(l0, l1), pk_bf16(l2, l3));
}

__device__ __forceinline__ void ldsm4(uint32_t* r, uint32_t addr) {
    asm volatile("ldmatrix.sync.aligned.m8n8.x4.shared.b16 {%0,%1,%2,%3}, [%4];"
                 : "=r"(r[0]), "=r"(r[1]), "=r"(r[2]), "=r"(r[3]) : "r"(addr));
}
__device__ __forceinline__ void ldsm4t(uint32_t* r, uint32_t addr) {
    asm volatile("ldmatrix.sync.aligned.m8n8.x4.trans.shared.b16 {%0,%1,%2,%3}, [%4];"
                 : "=r"(r[0]), "=r"(r[1]), "=r"(r[2]), "=r"(r[3]) : "r"(addr));
}
__device__ __forceinline__ void mma16816(float* c, const uint32_t* a, const uint32_t* b) {
    asm volatile("mma.sync.aligned.m16n8k16.row.col.f32.bf16.bf16.f32 "
                 "{%0,%1,%2,%3}, {%4,%5,%6,%7}, {%8,%9}, {%0,%1,%2,%3};"
                 : "+f"(c[0]), "+f"(c[1]), "+f"(c[2]), "+f"(c[3])
                 : "r"(a[0]), "r"(a[1]), "r"(a[2]), "r"(a[3]), "r"(b[0]), "r"(b[1]));
}
#define CP16(so, gp) \
    asm volatile("cp.async.cg.shared.global [%0], [%1], 16;\n" :: "r"(so), "l"(gp))
#define CP_COMMIT()  asm volatile("cp.async.commit_group;\n" ::: "memory")
#define CP_WAIT0()   asm volatile("cp.async.wait_group 0;\n" ::: "memory")

// ===========================================================================
// Tensor-core GEMM on pre-split bf16 operands (mma.sync path; tcgen05 is
// unavailable under this harness's compute_103 PTX target):
//   C = relu(A @ B + bias);  C written as fp32 (Cf) and/or bf16 hi/lo (Chi/Clo)
// bf16x3: hi*hi + hi*lo + lo*hi, fp32 accumulate.
// BM=256, BN=128, BK=64; 8 warps, warp tile 64x64; 1 CTA/SM, 192KB SMEM,
// cp.async double buffer. B kept natural [K][N], stored as two 64-col panels
// of 128B rows; ldmatrix.trans for the col operand.
// ===========================================================================
#define BM 256
#define BN 128
#define BK 64
// stage: Ahi 32KB | Alo 32KB | Bhi 16KB | Blo 16KB  = 96KB
#define ST_ALO 32768
#define ST_BHI 65536
#define ST_BLO 81920
#define ST_SZ  98304

__global__ __launch_bounds__(256, 1)
void gemm_bf16x3(const __nv_bfloat16* __restrict__ Ahi, const __nv_bfloat16* __restrict__ Alo,
                 const __nv_bfloat16* __restrict__ Bhi, const __nv_bfloat16* __restrict__ Blo,
                 const float* __restrict__ bias,
                 float* __restrict__ Cf,
                 __nv_bfloat16* __restrict__ Chi, __nv_bfloat16* __restrict__ Clo,
                 int M, int N, int K) {
    extern __shared__ char sm[];
    const int tid  = threadIdx.x;
    const int lane = tid & 31;
    const int wid  = tid >> 5;
    const int wm   = (wid & 3) * 64;    // warp M offset (0,64,128,192)
    const int wpn  = wid >> 2;          // warp N panel (0 or 1) -> cols wpn*64..+63
    const int bm   = blockIdx.y * BM;
    const int bn   = blockIdx.x * BN;

    const uint32_t smBase = (uint32_t)__cvta_generic_to_shared(sm);

    float acc[4][8][4];                 // [m16][n8][frag]
#pragma unroll
    for (int i = 0; i < 4; i++)
#pragma unroll
        for (int j = 0; j < 8; j++)
#pragma unroll
            for (int v = 0; v < 4; v++) acc[i][j][v] = 0.0f;

    auto load_stage = [&](int kt, int stg) {
        const uint32_t base = smBase + stg * ST_SZ;
        const size_t a0 = (size_t)bm * K + (size_t)kt * BK;
        const size_t b0 = (size_t)kt * BK * N + bn;
#pragma unroll
        for (int p = 0; p < 8; ++p) {              // A: 256 rows x 8 x 16B (hi+lo)
            const int c = tid + p * 256;
            const int r = c >> 3, ch = c & 7;
            const uint32_t so = base + r * 128 + (((ch ^ (r & 7)) & 7) << 4);
            const size_t g = a0 + (size_t)r * K + ch * 8;
            CP16(so, Ahi + g);
            CP16(so + ST_ALO, Alo + g);
        }
#pragma unroll
        for (int p = 0; p < 4; ++p) {              // B: 2 panels x 64 k-rows x 8 x 16B
            const int c = tid + p * 256;
            const int rr = c >> 3, ch = c & 7;     // rr = pn*64 + k
            const int k = rr & 63, pn = rr >> 6;
            const uint32_t so = base + ST_BHI + rr * 128 + (((ch ^ (k & 7)) & 7) << 4);
            const size_t g = b0 + (size_t)k * N + pn * 64 + ch * 8;
            CP16(so, Bhi + g);
            CP16(so + (ST_BLO - ST_BHI), Blo + g);
        }
        CP_COMMIT();
    };

    const int NT = K / BK;
    load_stage(0, 0);

    int stg = 0;
    for (int t = 0; t < NT; ++t) {
        CP_WAIT0();
        __syncthreads();
        if (t + 1 < NT) load_stage(t + 1, stg ^ 1);

        const uint32_t sb = smBase + stg * ST_SZ;
#pragma unroll
        for (int ks = 0; ks < 4; ++ks) {
            const int k16 = ks * 16;
            uint32_t ah[4][4], al[4][4], bh[4][4], bl[4][4];
#pragma unroll
            for (int mt = 0; mt < 4; ++mt) {
                const int r  = wm + mt * 16 + (lane & 15);
                const int kc = k16 + (lane >> 4) * 8;
                const uint32_t ad = sb + r * 128 + ((((kc >> 3) ^ (r & 7)) & 7) << 4);
                ldsm4(ah[mt], ad);
                ldsm4(al[mt], ad + ST_ALO);
            }
#pragma unroll
            for (int j = 0; j < 4; ++j) {          // 4 n16 tiles within this warp's panel
                const int kl = k16 + (lane & 15);
                const int nl = j * 16 + (lane >> 4) * 8;   // col within panel [0,64)
                const int rr = wpn * 64 + kl;
                const uint32_t bd = sb + ST_BHI + rr * 128 + ((((nl >> 3) ^ (kl & 7)) & 7) << 4);
                ldsm4t(bh[j], bd);
                ldsm4t(bl[j], bd + (ST_BLO - ST_BHI));
            }
#pragma unroll
            for (int mt = 0; mt < 4; ++mt)
#pragma unroll
                for (int nt = 0; nt < 8; ++nt) {
                    const int j = nt >> 1, s = (nt & 1) * 2;
                    mma16816(acc[mt][nt], ah[mt], &bh[j][s]);   // hi*hi
                    mma16816(acc[mt][nt], ah[mt], &bl[j][s]);   // hi*lo
                    mma16816(acc[mt][nt], al[mt], &bh[j][s]);   // lo*hi
                }
        }
        __syncthreads();
        stg ^= 1;
    }

    // Epilogue: bias + relu; fp32 and/or bf16 hi/lo stores
#pragma unroll
    for (int nt = 0; nt < 8; ++nt) {
        const int cn = bn + wpn * 64 + nt * 8 + (lane & 3) * 2;
        const float2 bv = *(const float2*)(bias + cn);
#pragma unroll
        for (int mt = 0; mt < 4; ++mt) {
            const int r0 = bm + wm + mt * 16 + (lane >> 2);
            float v[2][2];
            v[0][0] = fmaxf(acc[mt][nt][0] + bv.x, 0.0f);
            v[0][1] = fmaxf(acc[mt][nt][1] + bv.y, 0.0f);
            v[1][0] = fmaxf(acc[mt][nt][2] + bv.x, 0.0f);
            v[1][1] = fmaxf(acc[mt][nt][3] + bv.y, 0.0f);
#pragma unroll
            for (int h = 0; h < 2; ++h) {
                const size_t idx = (size_t)(r0 + h * 8) * N + cn;
                if (Cf) *(float2*)(Cf + idx) = make_float2(v[h][0], v[h][1]);
                if (Chi) {
                    __nv_bfloat16 h0 = __float2bfloat16(v[h][0]);
                    __nv_bfloat16 h1 = __float2bfloat16(v[h][1]);
                    __nv_bfloat16 l0 = __float2bfloat16(v[h][0] - __bfloat162float(h0));
                    __nv_bfloat16 l1 = __float2bfloat16(v[h][1] - __bfloat162float(h1));
                    *(uint32_t*)(Chi + idx) = pk_bf16(h0, h1);
                    *(uint32_t*)(Clo + idx) = pk_bf16(l0, l1);
                }
            }
        }
    }
}

// ---------------------------------------------------------------------------
// y_hat[r] = dot(feat_l[r,:], W3) + b3   (one warp per row)
// ---------------------------------------------------------------------------
__global__ void yhat_kernel(const float* __restrict__ feat_l,
                            const float* __restrict__ W3,
                            const float* __restrict__ b3,
                            float* __restrict__ out) {
    int warp = (blockIdx.x * blockDim.x + threadIdx.x) >> 5;
    int lane = threadIdx.x & 31;
    if (warp >= SL) return;
    const float* row = feat_l + (size_t)warp * H2;
    float s = 0.0f;
#pragma unroll
    for (int d = lane; d < H2; d += 32) s += row[d] * W3[d];
#pragma unroll
    for (int off = 16; off > 0; off >>= 1)
        s += __shfl_down_sync(0xFFFFFFFFu, s, off);
    if (lane == 0) out[warp] = s + b3[0];
}

// ---------------------------------------------------------------------------
// JAX threefry2x32 (20 rounds)
// ---------------------------------------------------------------------------
__device__ __forceinline__ uint32_t rotl32(uint32_t v, int d) {
    return (v << d) | (v >> (32 - d));
}
__device__ __forceinline__ void threefry2x32(uint32_t k0, uint32_t k1,
                                             uint32_t x0, uint32_t x1,
                                             uint32_t& o0, uint32_t& o1) {
    uint32_t k2 = k0 ^ k1 ^ 0x1BD11BDAu;
    x0 += k0; x1 += k1;
#define TF_RND(r) { x0 += x1; x1 = rotl32(x1, r); x1 ^= x0; }
    TF_RND(13) TF_RND(15) TF_RND(26) TF_RND(6)
    x0 += k1; x1 += k2 + 1u;
    TF_RND(17) TF_RND(29) TF_RND(16) TF_RND(24)
    x0 += k2; x1 += k0 + 2u;
    TF_RND(13) TF_RND(15) TF_RND(26) TF_RND(6)
    x0 += k0; x1 += k1 + 3u;
    TF_RND(17) TF_RND(29) TF_RND(16) TF_RND(24)
    x0 += k1; x1 += k2 + 4u;
    TF_RND(13) TF_RND(15) TF_RND(26) TF_RND(6)
    x0 += k2; x1 += k0 + 5u;
#undef TF_RND
    o0 = x0; o1 = x1;
}

// ---------------------------------------------------------------------------
// Pair sampling — JAX partitionable threefry (verified PASS R9/R11/R13)
// ---------------------------------------------------------------------------
__global__ void sample_pairs_kernel(const float* __restrict__ y_l,
                                    int* __restrict__ a_out,
                                    int* __restrict__ b_out) {
    int s = blockIdx.x * blockDim.x + threadIdx.x;
    if (s >= SU) return;

    uint32_t o0, o1;
    uint32_t ka0, ka1, kb0, kb1;
    threefry2x32(0u, 42u, 0u, 0u, ka0, ka1);
    threefry2x32(0u, 42u, 0u, 1u, kb0, kb1);

    uint32_t ka2_0, ka2_1, kb2_0, kb2_1;
    threefry2x32(ka0, ka1, 0u, 1u, ka2_0, ka2_1);
    threefry2x32(kb0, kb1, 0u, 1u, kb2_0, kb2_1);

    int a = -1, b = -1, a_first = 0, b_first = 0;
#pragma unroll
    for (int k = 0; k < K_TRIES; k++) {
        uint32_t i = (uint32_t)s * K_TRIES + k;
        threefry2x32(ka2_0, ka2_1, 0u, i, o0, o1);
        int ia = (int)((o0 ^ o1) & (SL - 1));
        threefry2x32(kb2_0, kb2_1, 0u, i, o0, o1);
        int ib = (int)((o0 ^ o1) & (SL - 1));
        if (k == 0) { a_first = ia; b_first = ib; }
        if (a < 0 && ia != ib && y_l[ia] != y_l[ib]) { a = ia; b = ib; }
    }
    if (a < 0) { a = a_first; b = b_first; }
    a_out[s] = a;
    b_out[s] = b;
}

// ---------------------------------------------------------------------------
// feat_comb[s] = k * feat_l[a] + (1-k) * feat_l[b]
// ---------------------------------------------------------------------------
__global__ void combine_kernel(const float* __restrict__ feat_l,
                               const float* __restrict__ y_l,
                               const float* __restrict__ y_u,
                               const int* __restrict__ a_idx,
                               const int* __restrict__ b_idx,
                               float* __restrict__ out) {
    int s = blockIdx.x;
    int a = a_idx[s], b = b_idx[s];
    float ya = y_l[a], yb = y_l[b];
    float kc = (y_u[s] - yb) / (ya - yb);
    float km = 1.0f - kc;
    const float4* fa = (const float4*)(feat_l + (size_t)a * H2);
    const float4* fb = (const float4*)(feat_l + (size_t)b * H2);
    float4* o = (float4*)(out + (size_t)s * H2);
    for (int d = threadIdx.x; d < H2 / 4; d += blockDim.x) {
        float4 va = fa[d], vb = fb[d], r;
        r.x = kc * va.x + km * vb.x;
        r.y = kc * va.y + km * vb.y;
        r.z = kc * va.z + km * vb.z;
        r.w = kc * va.w + km * vb.w;
        o[d] = r;
    }
}

// ---------------------------------------------------------------------------
// Launch
// ---------------------------------------------------------------------------
extern "C" void kernel_launch(void* const* d_in, const int* in_sizes, int n_in,
                              void* d_out, int out_size) {
    const float* X_l = (const float*)d_in[0];
    const float* y_l = (const float*)d_in[1];
    const float* X_u = (const float*)d_in[2];
    const float* y_u = (const float*)d_in[3];
    const float* W1  = (const float*)d_in[4];
    const float* b1  = (const float*)d_in[5];
    const float* W2  = (const float*)d_in[6];
    const float* b2  = (const float*)d_in[7];
    const float* W3  = (const float*)d_in[8];
    const float* b3  = (const float*)d_in[9];

    float* out = (float*)d_out;
    float* out_feat_u    = out;                       // [SU, H2]
    float* out_feat_comb = out + (size_t)SU * H2;     // [SU, H2]
    float* out_yhat      = out + (size_t)2 * SU * H2; // [SL, 1]

    __nv_bfloat16 *pXuh, *pXul, *pXlh, *pXll, *pW1h, *pW1l, *pW2h, *pW2l, *pHh, *pHl;
    float* pfl;
    int *pa, *pb;
    cudaGetSymbolAddress((void**)&pXuh, g_Xu_hi);
    cudaGetSymbolAddress((void**)&pXul, g_Xu_lo);
    cudaGetSymbolAddress((void**)&pXlh, g_Xl_hi);
    cudaGetSymbolAddress((void**)&pXll, g_Xl_lo);
    cudaGetSymbolAddress((void**)&pW1h, g_W1_hi);
    cudaGetSymbolAddress((void**)&pW1l, g_W1_lo);
    cudaGetSymbolAddress((void**)&pW2h, g_W2_hi);
    cudaGetSymbolAddress((void**)&pW2l, g_W2_lo);
    cudaGetSymbolAddress((void**)&pHh,  g_h_hi);
    cudaGetSymbolAddress((void**)&pHl,  g_h_lo);
    cudaGetSymbolAddress((void**)&pfl,  g_feat_l);
    cudaGetSymbolAddress((void**)&pa,   g_a);
    cudaGetSymbolAddress((void**)&pb,   g_b);

    cudaFuncSetAttribute(gemm_bf16x3,
                         cudaFuncAttributeMaxDynamicSharedMemorySize, 2 * ST_SZ);

    // --- one-time fp32 -> bf16 hi/lo splits
    auto cvt = [&](const float* src, __nv_bfloat16* hi, __nv_bfloat16* lo, size_t n) {
        int n4 = (int)(n / 4);
        cvt_hilo<<<(n4 + 255) / 256, 256>>>((const float4*)src, (uint2*)hi, (uint2*)lo, n4);
    };
    cvt(X_u, pXuh, pXul, (size_t)SU * DIM_X);
    cvt(X_l, pXlh, pXll, (size_t)SL * DIM_X);
    cvt(W1,  pW1h, pW1l, (size_t)DIM_X * H1);
    cvt(W2,  pW2h, pW2l, (size_t)H1 * H2);

    // --- unlabeled branch
    gemm_bf16x3<<<dim3(H1 / BN, SU / BM), 256, 2 * ST_SZ>>>(
        pXuh, pXul, pW1h, pW1l, b1, nullptr, pHh, pHl, SU, H1, DIM_X);
    gemm_bf16x3<<<dim3(H2 / BN, SU / BM), 256, 2 * ST_SZ>>>(
        pHh, pHl, pW2h, pW2l, b2, out_feat_u, nullptr, nullptr, SU, H2, H1);

    // --- labeled branch (reuses g_h)
    gemm_bf16x3<<<dim3(H1 / BN, SL / BM), 256, 2 * ST_SZ>>>(
        pXlh, pXll, pW1h, pW1l, b1, nullptr, pHh, pHl, SL, H1, DIM_X);
    gemm_bf16x3<<<dim3(H2 / BN, SL / BM), 256, 2 * ST_SZ>>>(
        pHh, pHl, pW2h, pW2l, b2, pfl, nullptr, nullptr, SL, H2, H1);

    // --- y_hat
    yhat_kernel<<<SL / 8, 256>>>(pfl, W3, b3, out_yhat);

    // --- pair sampling + combine
    sample_pairs_kernel<<<SU / 256, 256>>>(y_l, pa, pb);
    combine_kernel<<<SU, 128>>>(pfl, y_l, y_u, pa, pb, out_feat_comb);
}